// round 2
// baseline (speedup 1.0000x reference)
#include <cuda_runtime.h>
#include <math.h>

// ---------------- problem constants ----------------
#define NB    4
#define NS    3
#define NE    7
#define IMGSZ 256
#define PHS   8
#define HS    32      // IMG/PH
#define DMODEL 128
#define NHEAD 4
#define DKK   64
#define DCC   128
#define DHH   32
#define TEMBN 256
#define LKN   128
#define NGRP  16
#define EPSV  1e-5f

// ---------------- scratch (__device__ globals, zero-init; borders never written) --
__device__ float g_xp_pad[12 * 448 * 34 * 34];   // patchified, padded
__device__ float g_conv1 [12 * 128 * 32 * 32];   // conv1 out (= xp in (B,S,D,H,H))
__device__ float g_xn    [12 * 128 * 32 * 32];   // groupnormed
__device__ float g_q     [4096 * 256];           // q2 (Nq, NH*DK)
__device__ float g_oattn [4096 * 128];           // attention out, (Nq, DC) layout
__device__ float g_o2pad [4 * 128 * 34 * 34];    // outproj out, padded for conv2
__device__ float g_u     [4 * 7 * 256 * 256];    // unpatchified image (skip)
__device__ float g_cmod  [64];                   // modulation c (4 x 14)
__device__ float g_psum  [128];
__device__ float g_psq   [128];
__device__ float g_stats [8];                    // per-batch mean, inv_std

// ---------------- helpers ----------------
__device__ __forceinline__ float geluf(float v) {
    return 0.5f * v * (1.0f + erff(v * 0.70710678118654752f));
}

// ---------------- 1) pack x -> padded patchified layout (12,448,34,34) ----------
__global__ void k_pack(const float* __restrict__ x) {
    int idx = blockIdx.x * 256 + threadIdx.x;
    if (idx >= 12 * 448 * 34 * 34) return;
    int xx = idx % 34;
    int t  = idx / 34;
    int yy = t % 34;  t /= 34;
    int c  = t % 448;
    int n  = t / 448;
    float v = 0.f;
    if (xx > 0 && xx < 33 && yy > 0 && yy < 33) {
        int y = yy - 1, xq = xx - 1;
        int p1 = c / 56, rem = c % 56, p2 = rem / 7, e = rem % 7;
        v = x[((n * 7 + e) * 256 + (y * 8 + p1)) * 256 + (xq * 8 + p2)];
    }
    g_xp_pad[idx] = v;
}

// ---------------- 2/7) direct 3x3 conv (GEMM-style, smem staged per channel) ----
// MODE 1: conv1  (in=g_xp_pad Cin=448, out=g_conv1 Cout=128, +pos_embed)
// MODE 2: conv2  (in=g_o2pad  Cin=128, out=g_u unpatchified Cout=448)
template<int TM, int MODE>
__global__ void k_conv3x3(const float* __restrict__ wgt,
                          const float* __restrict__ bias,
                          const float* __restrict__ pos,
                          int Cin, int Cout) {
    const int CT = TM * 16;
    __shared__ float sW[CT * 9];
    __shared__ float sIn[3 * 34];

    const float* inp = (MODE == 1) ? g_xp_pad : g_o2pad;
    int y  = blockIdx.x;
    int m0 = blockIdx.y * CT;
    int n  = blockIdx.z;
    int tid = threadIdx.x;            // 128 threads
    int tx = tid & 7;                 // 8 pixel groups of 4
    int ty = tid >> 3;                // 16 out-channel groups of TM

    float acc[TM][4];
#pragma unroll
    for (int i = 0; i < TM; i++)
#pragma unroll
        for (int j = 0; j < 4; j++) acc[i][j] = 0.f;

    const float* inbase = inp + (size_t)n * Cin * 1156 + y * 34;

    for (int c = 0; c < Cin; c++) {
        __syncthreads();
        if (tid < 102) sIn[tid] = inbase[c * 1156 + tid];       // rows y..y+2 contiguous
        for (int i = tid; i < CT * 9; i += 128)
            sW[i] = wgt[((m0 + i / 9) * Cin + c) * 9 + (i % 9)];
        __syncthreads();

        float rin[3][6];
#pragma unroll
        for (int r = 0; r < 3; r++)
#pragma unroll
            for (int j = 0; j < 6; j++) rin[r][j] = sIn[r * 34 + tx * 4 + j];

#pragma unroll
        for (int tm = 0; tm < TM; tm++) {
            float w9[9];
#pragma unroll
            for (int t9 = 0; t9 < 9; t9++) w9[t9] = sW[(ty * TM + tm) * 9 + t9];
#pragma unroll
            for (int ky = 0; ky < 3; ky++)
#pragma unroll
                for (int kx = 0; kx < 3; kx++) {
                    float wv = w9[ky * 3 + kx];
#pragma unroll
                    for (int j = 0; j < 4; j++)
                        acc[tm][j] = fmaf(wv, rin[ky][j + kx], acc[tm][j]);
                }
        }
    }

#pragma unroll
    for (int tm = 0; tm < TM; tm++) {
        int o = m0 + ty * TM + tm;
        float bv = bias[o];
#pragma unroll
        for (int j = 0; j < 4; j++) {
            int xq = tx * 4 + j;
            float v = acc[tm][j] + bv;
            if (MODE == 1) {
                v += pos[o * 1024 + y * 32 + xq];
                g_conv1[((n * 128 + o) * 32 + y) * 32 + xq] = v;
            } else {
                int p1 = o / 56, rem = o % 56, p2 = rem / 7, e = rem % 7;
                g_u[(((size_t)n * 7 + e) * 256 + (y * 8 + p1)) * 256 + (xq * 8 + p2)] = v;
            }
        }
    }
}

// ---------------- 3) group norm (contiguous 24576-float chunks) ----------------
__global__ void k_gnorm(const float* __restrict__ gamma, const float* __restrict__ beta) {
    int b = blockIdx.x >> 4, g = blockIdx.x & 15;
    const int CH = 24576;
    size_t base = (size_t)b * 393216 + (size_t)g * CH;
    int tid = threadIdx.x;    // 256
    float s = 0.f, sq = 0.f;
    for (int i = tid; i < CH; i += 256) {
        float v = g_conv1[base + i];
        s += v; sq += v * v;
    }
#pragma unroll
    for (int off = 16; off; off >>= 1) {
        s  += __shfl_xor_sync(0xffffffffu, s,  off);
        sq += __shfl_xor_sync(0xffffffffu, sq, off);
    }
    __shared__ float rs[8], rq[8];
    int w = tid >> 5, lane = tid & 31;
    if (!lane) { rs[w] = s; rq[w] = sq; }
    __syncthreads();
    s = 0.f; sq = 0.f;
#pragma unroll
    for (int i = 0; i < 8; i++) { s += rs[i]; sq += rq[i]; }
    float mean = s / (float)CH;
    float var  = sq / (float)CH - mean * mean;
    float inv  = rsqrtf(var + EPSV);
    for (int i = tid; i < CH; i += 256) {
        int dch = g * 8 + i / 3072;
        g_xn[base + i] = (g_conv1[base + i] - mean) * inv * gamma[dch] + beta[dch];
    }
}

// ---------------- 4) q GEMM: (4096 x 256) = xn_rows(4096x384) @ w_eff^T --------
__global__ void k_qgemm(const float* __restrict__ w1, const float* __restrict__ b1,
                        const float* __restrict__ w2, const float* __restrict__ b2) {
    __shared__ float sA[32][65];
    __shared__ float sB[32][65];
    int n0 = blockIdx.x * 64, o0 = blockIdx.y * 64;
    int tid = threadIdx.x;   // 256
    float sw[3] = { w2[0], w2[1], w2[2] };
    float sws = sw[0] + sw[1] + sw[2];
    int tx = tid % 16, ty = tid / 16;
    float acc[4][4];
#pragma unroll
    for (int i = 0; i < 4; i++)
#pragma unroll
        for (int j = 0; j < 4; j++) acc[i][j] = 0.f;

    for (int kk = 0; kk < 384; kk += 32) {
        __syncthreads();
        for (int i = tid; i < 2048; i += 256) {
            int nl = i >> 5, kl = i & 31;
            sA[kl][nl] = g_xn[(size_t)(n0 + nl) * 384 + kk + kl];
        }
        for (int i = tid; i < 2048; i += 256) {
            int ol = i & 63, kl = i >> 6;
            int kg = kk + kl;
            sB[kl][ol] = w1[(o0 + ol) * 128 + kg / 3] * sw[kg % 3];
        }
        __syncthreads();
#pragma unroll
        for (int k = 0; k < 32; k++) {
            float a[4], bb[4];
#pragma unroll
            for (int j = 0; j < 4; j++) { a[j] = sA[k][ty * 4 + j]; bb[j] = sB[k][tx * 4 + j]; }
#pragma unroll
            for (int i = 0; i < 4; i++)
#pragma unroll
                for (int j = 0; j < 4; j++) acc[i][j] = fmaf(a[i], bb[j], acc[i][j]);
        }
    }
    float fb = b2[0];
#pragma unroll
    for (int i = 0; i < 4; i++)
#pragma unroll
        for (int j = 0; j < 4; j++) {
            int o = o0 + tx * 4 + j;
            g_q[(n0 + ty * 4 + i) * 256 + o] = acc[i][j] + b1[o] * sws + fb;
        }
}

// ---------------- 5) attention (one block per row r) ---------------------------
__global__ void k_attn(const float* __restrict__ kc, const float* __restrict__ vc) {
    int r = blockIdx.x;
    int tid = threadIdx.x;     // 128
    int w = tid >> 5, lane = tid & 31;
    __shared__ float sq[64];
    __shared__ float se[128];
    __shared__ float red[4], red2[4];
    __shared__ float oacc[4][32];

    if (tid < 64) sq[tid] = g_q[r * 64 + tid];
    __syncthreads();

    // score for l = tid
    const float4* krow = (const float4*)(kc + (size_t)r * 8192 + (size_t)tid * 64);
    float dot = 0.f;
#pragma unroll
    for (int i = 0; i < 16; i++) {
        float4 kv = krow[i];
        dot += kv.x * sq[i * 4] + kv.y * sq[i * 4 + 1] + kv.z * sq[i * 4 + 2] + kv.w * sq[i * 4 + 3];
    }
    dot *= 0.125f;

    float m = dot;
#pragma unroll
    for (int off = 16; off; off >>= 1) m = fmaxf(m, __shfl_xor_sync(0xffffffffu, m, off));
    if (!lane) red[w] = m;
    __syncthreads();
    m = fmaxf(fmaxf(red[0], red[1]), fmaxf(red[2], red[3]));

    float e = __expf(dot - m);
    se[tid] = e;
    float s = e;
#pragma unroll
    for (int off = 16; off; off >>= 1) s += __shfl_xor_sync(0xffffffffu, s, off);
    if (!lane) red2[w] = s;
    __syncthreads();                       // also publishes se[]
    float inv = 1.f / (red2[0] + red2[1] + red2[2] + red2[3]);

    // o[c] accumulation: warp w handles l in [w*32, w*32+32), lane = c
    const float* vbase = vc + (size_t)r * 4096;
    float a = 0.f;
#pragma unroll 4
    for (int li = 0; li < 32; li++) {
        int l = w * 32 + li;
        a = fmaf(se[l], vbase[l * 32 + lane], a);
    }
    oacc[w][lane] = a;
    __syncthreads();
    if (tid < 32) {
        float tot = oacc[0][tid] + oacc[1][tid] + oacc[2][tid] + oacc[3][tid];
        g_oattn[(r & 4095) * 128 + (r >> 12) * 32 + tid] = tot * inv;
    }
}

// ---------------- 6) out projection -> padded conv2 input ----------------------
__global__ void k_outproj(const float* __restrict__ w, const float* __restrict__ bias) {
    __shared__ float sIn[32][129];
    __shared__ float sWt[32][129];
    int b = blockIdx.y;
    int hw0 = blockIdx.x * 128;
    int tid = threadIdx.x;    // 256
    int tx = tid % 16, ty = tid / 16;
    float acc[8][8];
#pragma unroll
    for (int i = 0; i < 8; i++)
#pragma unroll
        for (int j = 0; j < 8; j++) acc[i][j] = 0.f;

    for (int cc = 0; cc < 128; cc += 32) {
        __syncthreads();
        for (int i = tid; i < 4096; i += 256) {
            int kl = i >> 7, hl = i & 127;
            sIn[kl][hl] = g_oattn[b * 131072 + (cc + kl) * 1024 + hw0 + hl];
        }
        for (int i = tid; i < 4096; i += 256) {
            int ol = i & 127, kl = i >> 7;
            sWt[kl][ol] = w[ol * 128 + cc + kl];
        }
        __syncthreads();
#pragma unroll 8
        for (int k = 0; k < 32; k++) {
            float a[8], bb[8];
#pragma unroll
            for (int i = 0; i < 8; i++) { a[i] = sWt[k][ty * 8 + i]; bb[i] = sIn[k][tx * 8 + i]; }
#pragma unroll
            for (int i = 0; i < 8; i++)
#pragma unroll
                for (int j = 0; j < 8; j++) acc[i][j] = fmaf(a[i], bb[j], acc[i][j]);
        }
    }
#pragma unroll
    for (int i = 0; i < 8; i++) {
        int o = ty * 8 + i;
        float bv = bias[o];
#pragma unroll
        for (int j = 0; j < 8; j++) {
            int hw = hw0 + tx * 8 + j;
            int y = hw >> 5, x2 = hw & 31;
            g_o2pad[((b * 128 + o) * 34 + y + 1) * 34 + x2 + 1] = acc[i][j] + bv;
        }
    }
}

// ---------------- 8) modulation c = silu(emb) @ mod_w^T + mod_b ----------------
__global__ void k_cmod(const float* __restrict__ emb, const float* __restrict__ mw,
                       const float* __restrict__ mb) {
    int t = threadIdx.x;
    if (t >= 56) return;
    int b = t / 14, j = t % 14;
    float acc = mb[j];
    for (int i = 0; i < 256; i++) {
        float v = emb[b * 256 + i];
        float sil = v / (1.f + __expf(-v));
        acc = fmaf(sil, mw[j * 256 + i], acc);
    }
    g_cmod[t] = acc;
}

// ---------------- 9/10) per-batch stats of u -----------------------------------
__global__ void k_upart() {
    int b = blockIdx.y, blk = blockIdx.x;       // 32 blocks per batch
    size_t base = (size_t)b * 458752 + (size_t)blk * 14336;
    int tid = threadIdx.x;  // 256
    float s = 0.f, sq = 0.f;
    for (int i = tid; i < 14336; i += 256) {
        float v = g_u[base + i];
        s += v; sq += v * v;
    }
#pragma unroll
    for (int off = 16; off; off >>= 1) {
        s  += __shfl_xor_sync(0xffffffffu, s,  off);
        sq += __shfl_xor_sync(0xffffffffu, sq, off);
    }
    __shared__ float rs[8], rq[8];
    int w = tid >> 5, lane = tid & 31;
    if (!lane) { rs[w] = s; rq[w] = sq; }
    __syncthreads();
    if (tid == 0) {
        float ts = 0.f, tq = 0.f;
#pragma unroll
        for (int i = 0; i < 8; i++) { ts += rs[i]; tq += rq[i]; }
        g_psum[b * 32 + blk] = ts;
        g_psq [b * 32 + blk] = tq;
    }
}

__global__ void k_ucomb() {
    int b = threadIdx.x;
    if (b < 4) {
        float s = 0.f, sq = 0.f;
        for (int i = 0; i < 32; i++) { s += g_psum[b * 32 + i]; sq += g_psq[b * 32 + i]; }
        float mean = s / 458752.f;
        float var  = sq / 458752.f - mean * mean;
        g_stats[b * 2]     = mean;
        g_stats[b * 2 + 1] = rsqrtf(var + EPSV);
    }
}

// ---------------- 11) final fused elementwise ----------------------------------
__global__ void k_final(const float* __restrict__ ew, const float* __restrict__ eb,
                        const float* __restrict__ fw, const float* __restrict__ fb,
                        float* __restrict__ out) {
    int b = blockIdx.y;
    int p = blockIdx.x * 256 + threadIdx.x;   // 65536 px per batch
    __shared__ float s_ew[98], s_eb[14], s_fw[49], s_fb[7], s_sc[7], s_sh[7];
    __shared__ float s_mean, s_istd;
    int t = threadIdx.x;
    if (t < 98) s_ew[t] = ew[t];
    if (t < 49) s_fw[t] = fw[t];
    if (t < 14) s_eb[t] = eb[t];
    if (t < 7)  { s_fb[t] = fb[t]; s_sc[t] = g_cmod[b * 14 + t]; s_sh[t] = g_cmod[b * 14 + 7 + t]; }
    if (t == 0) { s_mean = g_stats[b * 2]; s_istd = g_stats[b * 2 + 1]; }
    __syncthreads();

    float mean = s_mean, istd = s_istd;
    float uv[7], un[7];
#pragma unroll
    for (int e = 0; e < 7; e++) uv[e] = g_u[((size_t)b * 7 + e) * 65536 + p];
#pragma unroll
    for (int e = 0; e < 7; e++) un[e] = (uv[e] - mean) * istd * (1.f + s_sc[e]) + s_sh[e];

    float en[14];
#pragma unroll
    for (int j = 0; j < 14; j++) {
        float a = s_eb[j];
#pragma unroll
        for (int e = 0; e < 7; e++) a = fmaf(s_ew[j * 7 + e], un[e], a);
        en[j] = a;
    }
    float hf[7];
#pragma unroll
    for (int e = 0; e < 7; e++) hf[e] = geluf(un[e]) + en[e] * geluf(en[7 + e]);

#pragma unroll
    for (int o = 0; o < 7; o++) {
        float a = s_fb[o];
#pragma unroll
        for (int e = 0; e < 7; e++) a = fmaf(s_fw[o * 7 + e], hf[e], a);
        out[((size_t)b * 7 + o) * 65536 + p] = a + uv[o];
    }
}

// ---------------- launch --------------------------------------------------------
extern "C" void kernel_launch(void* const* d_in, const int* in_sizes, int n_in,
                              void* d_out, int out_size) {
    const float* x         = (const float*)d_in[0];
    const float* k_cond    = (const float*)d_in[1];
    const float* v_cond    = (const float*)d_in[2];
    const float* emb       = (const float*)d_in[3];
    const float* pos_embed = (const float*)d_in[4];
    const float* patch_w   = (const float*)d_in[5];
    const float* patch_b   = (const float*)d_in[6];
    const float* gn_gamma  = (const float*)d_in[7];
    const float* gn_beta   = (const float*)d_in[8];
    const float* fc1q_w    = (const float*)d_in[9];
    const float* fc1q_b    = (const float*)d_in[10];
    const float* fc2q_w    = (const float*)d_in[11];
    const float* fc2q_b    = (const float*)d_in[12];
    const float* outproj_w = (const float*)d_in[13];
    const float* outproj_b = (const float*)d_in[14];
    const float* unpatch_w = (const float*)d_in[15];
    const float* unpatch_b = (const float*)d_in[16];
    const float* mod_w     = (const float*)d_in[17];
    const float* mod_b     = (const float*)d_in[18];
    const float* enlarge_w = (const float*)d_in[19];
    const float* enlarge_b = (const float*)d_in[20];
    const float* ff2_w     = (const float*)d_in[21];
    const float* ff2_b     = (const float*)d_in[22];
    float* out = (float*)d_out;

    k_pack<<<24276, 256>>>(x);
    k_conv3x3<8, 1><<<dim3(32, 1, 12), 128>>>(patch_w, patch_b, pos_embed, 448, 128);
    k_gnorm<<<64, 256>>>(gn_gamma, gn_beta);
    k_qgemm<<<dim3(64, 4), 256>>>(fc1q_w, fc1q_b, fc2q_w, fc2q_b);
    k_attn<<<16384, 128>>>(k_cond, v_cond);
    k_outproj<<<dim3(8, 4), 256>>>(outproj_w, outproj_b);
    k_conv3x3<7, 2><<<dim3(32, 4, 4), 128>>>(unpatch_w, unpatch_b, (const float*)0, 128, 448);
    k_cmod<<<1, 64>>>(emb, mod_w, mod_b);
    k_upart<<<dim3(32, 4), 256>>>();
    k_ucomb<<<1, 32>>>();
    k_final<<<dim3(256, 4), 256>>>(enlarge_w, enlarge_b, ff2_w, ff2_b, out);
}